// round 9
// baseline (speedup 1.0000x reference)
#include <cuda_runtime.h>
#include <cuda_bf16.h>

#define IN_DIM   512
#define BATCH    8192
#define GRID_NUM 48
#define NCOEF    (GRID_NUM + 3)   // 51
#define NKNOT    (GRID_NUM + 1)   // 49
#define TILE     64               // dims per block -> 8 dim-tiles
#define THREADS  256
#define NBLOCKS  1184             // 148 SMs x 8 blocks: exactly one wave
#define NRG      148              // row-group columns per dim-tile (1184/8)
#define NRG_TOT  2048             // BATCH/4
#define CELL_LO  24               // x in [0,1) -> t in [24,48)
#define NCELL_S  24               // staged cells 24..47
#define NCOL_S   27               // coef columns needed: 24..50

__global__ __launch_bounds__(THREADS, 8) void bspline_fused_kernel(
    const float* __restrict__ x,
    const float* __restrict__ grid,
    const float* __restrict__ coef,
    float* __restrict__ y)
{
    __shared__ float4 s_quad[NCELL_S * TILE];   // 24.0 KB, [cell-24][d]
    __shared__ float  s_c[TILE * NCOL_S];       //  6.9 KB, [d][c-24]

    const int tid  = threadIdx.x;
    const int bid  = blockIdx.x;
    const int dim0 = (bid & 7) * TILE;
    const int rg0  = bid >> 3;                  // 0..147

    // Stage coef columns 24..50 for this block's 64 dims (contiguous 27-float runs).
    #pragma unroll
    for (int k = tid; k < TILE * NCOL_S; k += THREADS) {
        int d = k / NCOL_S, c = k - d * NCOL_S;
        s_c[k] = coef[(dim0 + d) * NCOEF + CELL_LO + c];
    }
    __syncthreads();

    // Build monomial quad table: s_c stride-27 LDS conflict-free; STS.128 banks 4d mod 32.
    #pragma unroll
    for (int k = tid; k < NCELL_S * TILE; k += THREADS) {
        int cell = k >> 6, d = k & (TILE - 1);
        const float* c = s_c + d * NCOL_S + cell;
        float c0 = c[0], c1 = c[1], c2 = c[2], c3 = c[3];
        float4 a;
        a.x = (c0 + 4.0f * c1 + c2) * (1.0f / 6.0f);
        a.y = (c2 - c0) * 0.5f;
        a.z = (c0 - 2.0f * c1 + c2) * 0.5f;
        a.w = (c3 - c0 + 3.0f * (c1 - c2)) * (1.0f / 6.0f);
        s_quad[k] = a;
    }

    const int d    = tid & (TILE - 1);
    const int rofs = tid >> 6;                  // 0..3
    const int col  = dim0 + d;
    const float glo  = grid[col * NKNOT];
    const float ghi  = grid[col * NKNOT + GRID_NUM];
    const float invh = (float)GRID_NUM / (ghi - glo);

    __syncthreads();

    const int idx0    = (rg0 * 4 + rofs) * IN_DIM + col;
    const int max_idx = ((NRG_TOT - 1) * 4 + rofs) * IN_DIM + col;
    const int K_OFF   = NRG * 4 * IN_DIM;       // 303104: per row-group-step offset

    // 3 full q=4 groups: k = 0..11, always in-range (rg0+11*148 <= 1923 < 2048).
    #pragma unroll
    for (int it = 0; it < 3; ++it) {
        const int base = idx0 + it * 4 * K_OFF;
        float xv[4], res[4];
        #pragma unroll
        for (int q = 0; q < 4; ++q)
            xv[q] = x[base + q * K_OFF];
        #pragma unroll
        for (int q = 0; q < 4; ++q) {
            float t = (xv[q] - glo) * invh;
            int cell = (int)t;
            cell = max(0, min(cell, GRID_NUM - 1));
            float u = t - (float)cell;
            int cs = cell - CELL_LO;
            float4 a;
            if ((unsigned)cs < (unsigned)NCELL_S) {
                a = s_quad[cs * TILE + d];      // conflict-free LDS.128
            } else {                            // never taken for in-range x
                const float* c = coef + col * NCOEF + cell;
                float c0 = c[0], c1 = c[1], c2 = c[2], c3 = c[3];
                a.x = (c0 + 4.0f * c1 + c2) * (1.0f / 6.0f);
                a.y = (c2 - c0) * 0.5f;
                a.z = (c0 - 2.0f * c1 + c2) * 0.5f;
                a.w = (c3 - c0 + 3.0f * (c1 - c2)) * (1.0f / 6.0f);
            }
            res[q] = fmaf(fmaf(fmaf(a.w, u, a.z), u, a.y), u, a.x);
        }
        #pragma unroll
        for (int q = 0; q < 4; ++q)
            y[base + q * K_OFF] = res[q];
    }

    // Tail q=2 group: k=12 in-range; k=13 clamped (duplicate rows write identical values).
    {
        const int i12 = idx0 + 12 * K_OFF;
        const int i13 = min(idx0 + 13 * K_OFF, max_idx);
        float xv[2], res[2];
        xv[0] = x[i12];
        xv[1] = x[i13];
        #pragma unroll
        for (int q = 0; q < 2; ++q) {
            float t = (xv[q] - glo) * invh;
            int cell = (int)t;
            cell = max(0, min(cell, GRID_NUM - 1));
            float u = t - (float)cell;
            int cs = cell - CELL_LO;
            float4 a;
            if ((unsigned)cs < (unsigned)NCELL_S) {
                a = s_quad[cs * TILE + d];
            } else {
                const float* c = coef + col * NCOEF + cell;
                float c0 = c[0], c1 = c[1], c2 = c[2], c3 = c[3];
                a.x = (c0 + 4.0f * c1 + c2) * (1.0f / 6.0f);
                a.y = (c2 - c0) * 0.5f;
                a.z = (c0 - 2.0f * c1 + c2) * 0.5f;
                a.w = (c3 - c0 + 3.0f * (c1 - c2)) * (1.0f / 6.0f);
            }
            res[q] = fmaf(fmaf(fmaf(a.w, u, a.z), u, a.y), u, a.x);
        }
        y[i12] = res[0];
        y[i13] = res[1];
    }
}

extern "C" void kernel_launch(void* const* d_in, const int* in_sizes, int n_in,
                              void* d_out, int out_size) {
    const float* x    = (const float*)d_in[0];
    const float* grid = (const float*)d_in[1];
    const float* coef = (const float*)d_in[2];
    float* y = (float*)d_out;

    bspline_fused_kernel<<<NBLOCKS, THREADS>>>(x, grid, coef, y);
}